// round 9
// baseline (speedup 1.0000x reference)
#include <cuda_runtime.h>
#include <math.h>

#define B_ 2
#define T_ 2048
#define D_ 512
#define K_ 64
#define TT 32        // t-tile per block
#define WP 100       // padded sq row stride (16B-aligned rows)
#define MP 96        // E row stride

typedef unsigned long long u64;

// packed dual-fp32 ops (sm_10x f32x2; PTX-only)
#define FMA2(d, a, b, c) \
    asm("fma.rn.f32x2 %0, %1, %2, %3;" : "=l"(d) : "l"(a), "l"(b), "l"(c))
#define ADD2(d, a, b) \
    asm("add.rn.f32x2 %0, %1, %2;" : "=l"(d) : "l"(a), "l"(b))
#define PACKDUP(d, x) \
    asm("mov.b64 %0, {%1, %1};" : "=l"(d) : "f"(x))

// 8MB scratch for q = gelu(conv1d(x)) in [b][d][t] layout
__device__ float g_q[B_ * D_ * T_];

__device__ __forceinline__ float gelu_exact(float v) {
    return 0.5f * v * (1.f + erff(v * 0.7071067811865476f));
}

// ---------------------------------------------------------------------------
// Kernel A: q = gelu(conv1d(x)); 8 t per thread, float4 I/O
// ---------------------------------------------------------------------------
__global__ void conv_gelu_kernel(const float* __restrict__ x,
                                 const float* __restrict__ w,
                                 const float* __restrict__ bias) {
    int d = blockIdx.y, b = blockIdx.z;
    int t = (blockIdx.x * 128 + threadIdx.x) * 8;
    float w0 = w[d * 3 + 0], w1 = w[d * 3 + 1], w2 = w[d * 3 + 2];
    float bb = bias[d];
    const float* xb = x + b * T_;
    float xv[10];
    float4 A  = *(const float4*)(xb + t);
    float4 Bv = *(const float4*)(xb + t + 4);
    xv[1] = A.x;  xv[2] = A.y;  xv[3] = A.z;  xv[4] = A.w;
    xv[5] = Bv.x; xv[6] = Bv.y; xv[7] = Bv.z; xv[8] = Bv.w;
    xv[0] = (t > 0)        ? xb[t - 1] : 0.f;
    xv[9] = (t + 8 < T_)   ? xb[t + 8] : 0.f;
    float o[8];
    #pragma unroll
    for (int e = 0; e < 8; e++) {
        float v = fmaf(w0, xv[e], fmaf(w1, xv[e + 1], w2 * xv[e + 2])) + bb;
        o[e] = gelu_exact(v);
    }
    float* op = g_q + (size_t)(b * D_ + d) * T_ + t;
    *(float4*)op       = make_float4(o[0], o[1], o[2], o[3]);
    *(float4*)(op + 4) = make_float4(o[4], o[5], o[6], o[7]);
}

// ---------------------------------------------------------------------------
// Kernel B: fused banded energy + softmax + context. 1024 threads/block.
// sq[d][w] = q[d][t0-64+w], w in [0,96). Band for row t: w in [t+1, t+64].
// smem: sq[512][100] + E0[32][96] + E1[32][96] = 229,376 B
// Window load: cp.async, each 128-thread D-group loads its own 64 rows and
// syncs on a named barrier -> energy starts per-group without a full-block wait.
// ---------------------------------------------------------------------------
extern __shared__ float smem[];

__global__ void __launch_bounds__(1024, 1)
attn_kernel(const float* __restrict__ gate, float* __restrict__ out) {
    float* sq = smem;                     // [512][100]
    float* E0 = smem + D_ * WP;           // [32][96]
    float* E1 = E0 + TT * MP;             // [32][96]

    const int tid = threadIdx.x;
    const int b   = blockIdx.y;
    const int t0  = blockIdx.x * TT;
    const float tgate = tanhf(gate[0]);

    const int qz = tid >> 7;      // D group (0..7)
    const int r  = tid & 127;

    // ---- window load: cp.async per D-group, named-barrier sync ----
    {
        const float* qbase = g_q + (size_t)b * D_ * T_
                             + (size_t)(64 * qz) * T_ + t0 - 64;
        float* sbase = sq + 64 * qz * WP;
        #pragma unroll
        for (int k = 0; k < 12; ++k) {
            int f  = r + k * 128;            // quad index over 64 rows x 24 quads
            int dl = f / 24, q = f - dl * 24;
            int wq = 4 * q;
            const float* src = qbase + (size_t)dl * T_ + wq;
            unsigned daddr =
                (unsigned)__cvta_generic_to_shared(sbase + dl * WP + wq);
            if (t0 - 64 + wq >= 0)
                asm volatile("cp.async.ca.shared.global [%0], [%1], 16;"
                             :: "r"(daddr), "l"(src));
            else  // zero-fill left pad (src not dereferenced)
                asm volatile("cp.async.ca.shared.global [%0], [%1], 16, 0;"
                             :: "r"(daddr), "l"(src));
        }
        asm volatile("cp.async.commit_group;");
        asm volatile("cp.async.wait_group 0;" ::: "memory");
        asm volatile("bar.sync %0, %1;" :: "r"(qz + 1), "r"(128) : "memory");
    }

    // ---- energy: 32 x 96 rect, 4 consecutive t x 6 w-pairs, D in 8 groups ----
    {
        const int tx = r & 15;        // w pair-group: w = 2*tx + 32*j (+0/1)
        const int ty = r >> 4;        // t quad: t = 4*ty + i, i=0..3
        u64 acc2[4][3];
        #pragma unroll
        for (int i = 0; i < 4; i++)
            #pragma unroll
            for (int j = 0; j < 3; j++) acc2[i][j] = 0ull;

        const float* sqd = sq + qz * 64 * WP;
        #pragma unroll 4
        for (int d = 0; d < 64; ++d) {
            const float* row = sqd + d * WP;
            float4 af = *(const float4*)(row + 64 + 4 * ty);  // broadcast LDS.128
            u64 a2[4];
            PACKDUP(a2[0], af.x);
            PACKDUP(a2[1], af.y);
            PACKDUP(a2[2], af.z);
            PACKDUP(a2[3], af.w);
            u64 bv2[3];
            #pragma unroll
            for (int j = 0; j < 3; j++)
                bv2[j] = *(const u64*)(row + 2 * tx + 32 * j);
            #pragma unroll
            for (int i = 0; i < 4; i++)
                #pragma unroll
                for (int j = 0; j < 3; j++)
                    FMA2(acc2[i][j], a2[i], bv2[j], acc2[i][j]);
        }
        // accumulate 8 partials into 2 buffers in 4 phases
        float* Eo = (qz & 1) ? E1 : E0;
        const int phase = qz >> 1;
        if (phase == 0) {
            #pragma unroll
            for (int i = 0; i < 4; i++)
                #pragma unroll
                for (int j = 0; j < 3; j++)
                    *(u64*)(Eo + (4 * ty + i) * MP + 2 * tx + 32 * j) = acc2[i][j];
        }
        __syncthreads();
        #pragma unroll
        for (int p = 1; p < 4; ++p) {
            if (phase == p) {
                #pragma unroll
                for (int i = 0; i < 4; i++)
                    #pragma unroll
                    for (int j = 0; j < 3; j++) {
                        u64* ptr = (u64*)(Eo + (4 * ty + i) * MP + 2 * tx + 32 * j);
                        u64 v = *ptr;
                        ADD2(v, v, acc2[i][j]);
                        *ptr = v;
                    }
            }
            __syncthreads();
        }
    }

    // ---- softmax over k; band w in [t+1, t+64]; attn into E0, zero elsewhere ----
    {
        const int t = tid >> 5, lane = tid & 31;  // one warp per t row
        const float S = 0.04419417382415922f;     // 1/sqrt(512)
        float e1 = E0[t * MP + t + 1 + lane]  + E1[t * MP + t + 1 + lane];
        float e2 = E0[t * MP + t + 33 + lane] + E1[t * MP + t + 33 + lane];
        float mx = fmaxf(e1, e2);
        #pragma unroll
        for (int o = 16; o; o >>= 1) mx = fmaxf(mx, __shfl_xor_sync(0xffffffffu, mx, o));
        float p1 = expf((e1 - mx) * S);
        float p2 = expf((e2 - mx) * S);
        float sm = p1 + p2;
        #pragma unroll
        for (int o = 16; o; o >>= 1) sm += __shfl_xor_sync(0xffffffffu, sm, o);
        float inv = 1.f / sm;
        E0[t * MP + lane]      = 0.f;
        E0[t * MP + lane + 32] = 0.f;
        E0[t * MP + lane + 64] = 0.f;
        E0[t * MP + t + 1 + lane]  = p1 * inv;
        E0[t * MP + t + 33 + lane] = p2 * inv;
    }
    __syncthreads();

    // ---- context: C[t][d] = sum_w attn[t][w] * sq[d][w]; 4t x 4d, LDS.128 ----
    {
        const int tx = tid & 127;  // d lane: d = tx + 128*j
        const int ty = tid >> 7;   // t group: t = 4*ty + i (consecutive)
        const int w0 = 4 * ty;     // band union [4ty+1, 4ty+67] within [w0, w0+68)
        u64 acc2[4][4];
        #pragma unroll
        for (int i = 0; i < 4; i++)
            #pragma unroll
            for (int j = 0; j < 4; j++) acc2[i][j] = 0ull;

        const float* bbase = sq + tx * WP;
        const float* abase = E0 + 4 * ty * MP;
        #pragma unroll 2
        for (int s = 0; s < 17; ++s) {
            const int w = w0 + 4 * s;
            ulonglong2 av[4];
            #pragma unroll
            for (int i = 0; i < 4; i++)
                av[i] = *(const ulonglong2*)(abase + i * MP + w);
            #pragma unroll
            for (int j = 0; j < 4; j++) {
                ulonglong2 bv = *(const ulonglong2*)(bbase + j * 128 * WP + w);
                #pragma unroll
                for (int i = 0; i < 4; i++) {
                    FMA2(acc2[i][j], av[i].x, bv.x, acc2[i][j]);
                    FMA2(acc2[i][j], av[i].y, bv.y, acc2[i][j]);
                }
            }
        }
        // horizontal add + direct STG.128: 4 consecutive t per thread
        #pragma unroll
        for (int j = 0; j < 4; j++) {
            float c[4];
            #pragma unroll
            for (int i = 0; i < 4; i++) {
                float2 p = *(float2*)&acc2[i][j];
                c[i] = (p.x + p.y) * tgate;
            }
            float* op = out + (size_t)(b * D_ + tx + 128 * j) * T_ + t0 + 4 * ty;
            *(float4*)op = make_float4(c[0], c[1], c[2], c[3]);
        }
    }
}

// ---------------------------------------------------------------------------
extern "C" void kernel_launch(void* const* d_in, const int* in_sizes, int n_in,
                              void* d_out, int out_size) {
    const float* x      = (const float*)d_in[0];  // (2,1,2048)
    const float* conv_w = (const float*)d_in[1];  // (512,1,3)
    const float* conv_b = (const float*)d_in[2];  // (512,)
    const float* gate   = (const float*)d_in[3];  // scalar
    float* out = (float*)d_out;                   // (2,512,2048)

    (void)in_sizes; (void)n_in; (void)out_size;

    dim3 gA(T_ / 1024, D_, B_);
    conv_gelu_kernel<<<gA, 128>>>(x, conv_w, conv_b);

    const int smem_bytes = (D_ * WP + 2 * TT * MP) * (int)sizeof(float); // 229,376
    cudaFuncSetAttribute(attn_kernel, cudaFuncAttributeMaxDynamicSharedMemorySize, smem_bytes);
    dim3 gB(T_ / TT, B_);
    attn_kernel<<<gB, 1024, smem_bytes>>>(gate, out);
}

// round 10
// speedup vs baseline: 1.0831x; 1.0831x over previous
#include <cuda_runtime.h>
#include <math.h>

#define B_ 2
#define T_ 2048
#define D_ 512
#define K_ 64
#define TT 32        // t-tile per block
#define WP 100       // padded sq row stride (16B-aligned rows)
#define MP 96        // E row stride

typedef unsigned long long u64;

// packed dual-fp32 ops (sm_10x f32x2; PTX-only)
#define FMA2(d, a, b, c) \
    asm("fma.rn.f32x2 %0, %1, %2, %3;" : "=l"(d) : "l"(a), "l"(b), "l"(c))
#define ADD2(d, a, b) \
    asm("add.rn.f32x2 %0, %1, %2;" : "=l"(d) : "l"(a), "l"(b))
#define PACKDUP(d, x) \
    asm("mov.b64 %0, {%1, %1};" : "=l"(d) : "f"(x))

// 8MB scratch for q = gelu(conv1d(x)) in [b][d][t] layout
__device__ float g_q[B_ * D_ * T_];

__device__ __forceinline__ float gelu_exact(float v) {
    return 0.5f * v * (1.f + erff(v * 0.7071067811865476f));
}

// ---------------------------------------------------------------------------
// Kernel A: q = gelu(conv1d(x)); 8 t per thread, float4 I/O
// ---------------------------------------------------------------------------
__global__ void conv_gelu_kernel(const float* __restrict__ x,
                                 const float* __restrict__ w,
                                 const float* __restrict__ bias) {
    int d = blockIdx.y, b = blockIdx.z;
    int t = (blockIdx.x * 128 + threadIdx.x) * 8;
    float w0 = w[d * 3 + 0], w1 = w[d * 3 + 1], w2 = w[d * 3 + 2];
    float bb = bias[d];
    const float* xb = x + b * T_;
    float xv[10];
    float4 A  = *(const float4*)(xb + t);
    float4 Bv = *(const float4*)(xb + t + 4);
    xv[1] = A.x;  xv[2] = A.y;  xv[3] = A.z;  xv[4] = A.w;
    xv[5] = Bv.x; xv[6] = Bv.y; xv[7] = Bv.z; xv[8] = Bv.w;
    xv[0] = (t > 0)        ? xb[t - 1] : 0.f;
    xv[9] = (t + 8 < T_)   ? xb[t + 8] : 0.f;
    float o[8];
    #pragma unroll
    for (int e = 0; e < 8; e++) {
        float v = fmaf(w0, xv[e], fmaf(w1, xv[e + 1], w2 * xv[e + 2])) + bb;
        o[e] = gelu_exact(v);
    }
    float* op = g_q + (size_t)(b * D_ + d) * T_ + t;
    *(float4*)op       = make_float4(o[0], o[1], o[2], o[3]);
    *(float4*)(op + 4) = make_float4(o[4], o[5], o[6], o[7]);
}

// ---------------------------------------------------------------------------
// Kernel B: fused banded energy + softmax + context. 512 threads/block.
// sq[d][w] = q[d][t0-64+w], w in [0,96). Band for row t: w in [t+1, t+64].
// smem: sq[512][100] + E0[32][96] + E1[32][96] = 229,376 B
// Energy: 8 groups of 64 threads, 64 d each, per-thread tile 4t x 12w.
// Context: per-thread tile 8t x 4d.
// ---------------------------------------------------------------------------
extern __shared__ float smem[];

__global__ void __launch_bounds__(512, 1)
attn_kernel(const float* __restrict__ gate, float* __restrict__ out) {
    float* sq = smem;                     // [512][100]
    float* E0 = smem + D_ * WP;           // [32][96]
    float* E1 = E0 + TT * MP;             // [32][96]

    const int tid = threadIdx.x;
    const int b   = blockIdx.y;
    const int t0  = blockIdx.x * TT;
    const float tgate = tanhf(gate[0]);

    const int qz = tid >> 6;      // D group (0..7), 64 threads each
    const int r  = tid & 63;

    // ---- window load: cp.async per D-group (64 rows), named-barrier sync ----
    {
        const float* qbase = g_q + (size_t)b * D_ * T_
                             + (size_t)(64 * qz) * T_ + t0 - 64;
        float* sbase = sq + 64 * qz * WP;
        #pragma unroll
        for (int k = 0; k < 24; ++k) {
            int f  = r + k * 64;             // quad index over 64 rows x 24 quads
            int dl = f / 24, q = f - dl * 24;
            int wq = 4 * q;
            const float* src = qbase + (size_t)dl * T_ + wq;
            unsigned daddr =
                (unsigned)__cvta_generic_to_shared(sbase + dl * WP + wq);
            if (t0 - 64 + wq >= 0)
                asm volatile("cp.async.ca.shared.global [%0], [%1], 16;"
                             :: "r"(daddr), "l"(src));
            else  // zero-fill left pad
                asm volatile("cp.async.ca.shared.global [%0], [%1], 16, 0;"
                             :: "r"(daddr), "l"(src));
        }
        asm volatile("cp.async.commit_group;");
        asm volatile("cp.async.wait_group 0;" ::: "memory");
        asm volatile("bar.sync %0, %1;" :: "r"(qz + 1), "r"(64) : "memory");
    }

    // ---- energy: 32 x 96 rect; group tile 4t x 12w per thread, 64 d-iters ----
    {
        const int tx = r & 7;         // w pair: w = 2*tx + 16*j (+0/1), j=0..5
        const int ty = r >> 3;        // t quad: t = 4*ty + i, i=0..3
        u64 acc2[4][6];
        #pragma unroll
        for (int i = 0; i < 4; i++)
            #pragma unroll
            for (int j = 0; j < 6; j++) acc2[i][j] = 0ull;

        const float* sqd = sq + qz * 64 * WP;
        #pragma unroll 2
        for (int d = 0; d < 64; ++d) {
            const float* row = sqd + d * WP;
            float4 af = *(const float4*)(row + 64 + 4 * ty);  // broadcast LDS.128
            u64 a2[4];
            PACKDUP(a2[0], af.x);
            PACKDUP(a2[1], af.y);
            PACKDUP(a2[2], af.z);
            PACKDUP(a2[3], af.w);
            u64 bv2[6];
            #pragma unroll
            for (int j = 0; j < 6; j++)
                bv2[j] = *(const u64*)(row + 2 * tx + 16 * j);
            #pragma unroll
            for (int i = 0; i < 4; i++)
                #pragma unroll
                for (int j = 0; j < 6; j++)
                    FMA2(acc2[i][j], a2[i], bv2[j], acc2[i][j]);
        }
        // accumulate 8 group-partials into 2 buffers in 4 phases
        float* Eo = (qz & 1) ? E1 : E0;
        const int phase = qz >> 1;
        if (phase == 0) {
            #pragma unroll
            for (int i = 0; i < 4; i++)
                #pragma unroll
                for (int j = 0; j < 6; j++)
                    *(u64*)(Eo + (4 * ty + i) * MP + 2 * tx + 16 * j) = acc2[i][j];
        }
        __syncthreads();
        #pragma unroll
        for (int p = 1; p < 4; ++p) {
            if (phase == p) {
                #pragma unroll
                for (int i = 0; i < 4; i++)
                    #pragma unroll
                    for (int j = 0; j < 6; j++) {
                        u64* ptr = (u64*)(Eo + (4 * ty + i) * MP + 2 * tx + 16 * j);
                        u64 v = *ptr;
                        ADD2(v, v, acc2[i][j]);
                        *ptr = v;
                    }
            }
            __syncthreads();
        }
    }

    // ---- softmax over k; band w in [t+1, t+64]; attn into E0, zeros elsewhere ----
    {
        const int warp = tid >> 5, lane = tid & 31;  // 16 warps, 2 rows each
        const float S = 0.04419417382415922f;        // 1/sqrt(512)
        #pragma unroll
        for (int t = warp; t < TT; t += 16) {
            float e1 = E0[t * MP + t + 1 + lane]  + E1[t * MP + t + 1 + lane];
            float e2 = E0[t * MP + t + 33 + lane] + E1[t * MP + t + 33 + lane];
            float mx = fmaxf(e1, e2);
            #pragma unroll
            for (int o = 16; o; o >>= 1) mx = fmaxf(mx, __shfl_xor_sync(0xffffffffu, mx, o));
            float p1 = __expf((e1 - mx) * S);
            float p2 = __expf((e2 - mx) * S);
            float sm = p1 + p2;
            #pragma unroll
            for (int o = 16; o; o >>= 1) sm += __shfl_xor_sync(0xffffffffu, sm, o);
            float inv = 1.f / sm;
            E0[t * MP + lane]      = 0.f;
            E0[t * MP + lane + 32] = 0.f;
            E0[t * MP + lane + 64] = 0.f;
            E0[t * MP + t + 1 + lane]  = p1 * inv;
            E0[t * MP + t + 33 + lane] = p2 * inv;
        }
    }
    __syncthreads();

    // ---- context: C[t][d] = sum_w attn[t][w] * sq[d][w]; 8t x 4d per thread ----
    {
        const int tx = tid & 127;  // d lane: d = tx + 128*j, j=0..3
        const int ty = tid >> 7;   // t group: t = 8*ty + i, i=0..7
        const int w0 = 8 * ty;     // band union [8ty+1, 8ty+71] within [w0, w0+72)
        u64 acc2[8][4];
        #pragma unroll
        for (int i = 0; i < 8; i++)
            #pragma unroll
            for (int j = 0; j < 4; j++) acc2[i][j] = 0ull;

        const float* bbase = sq + tx * WP;
        const float* abase = E0 + 8 * ty * MP;
        #pragma unroll 2
        for (int s = 0; s < 18; ++s) {
            const int w = w0 + 4 * s;
            // i in two chunks of 4 to bound register pressure
            #pragma unroll
            for (int ih = 0; ih < 2; ++ih) {
                ulonglong2 av[4];
                #pragma unroll
                for (int i = 0; i < 4; i++)
                    av[i] = *(const ulonglong2*)(abase + (4 * ih + i) * MP + w);
                #pragma unroll
                for (int j = 0; j < 4; j++) {
                    ulonglong2 bv = *(const ulonglong2*)(bbase + j * 128 * WP + w);
                    #pragma unroll
                    for (int i = 0; i < 4; i++) {
                        FMA2(acc2[4 * ih + i][j], av[i].x, bv.x, acc2[4 * ih + i][j]);
                        FMA2(acc2[4 * ih + i][j], av[i].y, bv.y, acc2[4 * ih + i][j]);
                    }
                }
            }
        }
        // horizontal add + direct STG.128: 8 consecutive t per thread
        #pragma unroll
        for (int j = 0; j < 4; j++) {
            float c[8];
            #pragma unroll
            for (int i = 0; i < 8; i++) {
                float2 p = *(float2*)&acc2[i][j];
                c[i] = (p.x + p.y) * tgate;
            }
            float* op = out + (size_t)(b * D_ + tx + 128 * j) * T_ + t0 + 8 * ty;
            *(float4*)op       = make_float4(c[0], c[1], c[2], c[3]);
            *(float4*)(op + 4) = make_float4(c[4], c[5], c[6], c[7]);
        }
    }
}

// ---------------------------------------------------------------------------
extern "C" void kernel_launch(void* const* d_in, const int* in_sizes, int n_in,
                              void* d_out, int out_size) {
    const float* x      = (const float*)d_in[0];  // (2,1,2048)
    const float* conv_w = (const float*)d_in[1];  // (512,1,3)
    const float* conv_b = (const float*)d_in[2];  // (512,)
    const float* gate   = (const float*)d_in[3];  // scalar
    float* out = (float*)d_out;                   // (2,512,2048)

    (void)in_sizes; (void)n_in; (void)out_size;

    dim3 gA(T_ / 1024, D_, B_);
    conv_gelu_kernel<<<gA, 128>>>(x, conv_w, conv_b);

    const int smem_bytes = (D_ * WP + 2 * TT * MP) * (int)sizeof(float); // 229,376
    cudaFuncSetAttribute(attn_kernel, cudaFuncAttributeMaxDynamicSharedMemorySize, smem_bytes);
    dim3 gB(T_ / TT, B_);
    attn_kernel<<<gB, 512, smem_bytes>>>(gate, out);
}

// round 11
// speedup vs baseline: 1.1604x; 1.0714x over previous
#include <cuda_runtime.h>
#include <math.h>

#define B_ 2
#define T_ 2048
#define D_ 512
#define K_ 64
#define TT 32        // t-tile per block
#define WP 100       // padded sq row stride (16B-aligned rows)
#define MP 96        // E row stride

typedef unsigned long long u64;

// packed dual-fp32 ops (sm_10x f32x2; PTX-only)
#define FMA2(d, a, b, c) \
    asm("fma.rn.f32x2 %0, %1, %2, %3;" : "=l"(d) : "l"(a), "l"(b), "l"(c))
#define ADD2(d, a, b) \
    asm("add.rn.f32x2 %0, %1, %2;" : "=l"(d) : "l"(a), "l"(b))
#define PACKDUP(d, x) \
    asm("mov.b64 %0, {%1, %1};" : "=l"(d) : "f"(x))

// 8MB scratch for q = gelu(conv1d(x)) in [b][d][t] layout
__device__ float g_q[B_ * D_ * T_];

__device__ __forceinline__ float gelu_exact(float v) {
    return 0.5f * v * (1.f + erff(v * 0.7071067811865476f));
}

// ---------------------------------------------------------------------------
// Kernel A: q = gelu(conv1d(x)); 8 t per thread, float4 I/O
// ---------------------------------------------------------------------------
__global__ void conv_gelu_kernel(const float* __restrict__ x,
                                 const float* __restrict__ w,
                                 const float* __restrict__ bias) {
    int d = blockIdx.y, b = blockIdx.z;
    int t = (blockIdx.x * 128 + threadIdx.x) * 8;
    float w0 = w[d * 3 + 0], w1 = w[d * 3 + 1], w2 = w[d * 3 + 2];
    float bb = bias[d];
    const float* xb = x + b * T_;
    float xv[10];
    float4 A  = *(const float4*)(xb + t);
    float4 Bv = *(const float4*)(xb + t + 4);
    xv[1] = A.x;  xv[2] = A.y;  xv[3] = A.z;  xv[4] = A.w;
    xv[5] = Bv.x; xv[6] = Bv.y; xv[7] = Bv.z; xv[8] = Bv.w;
    xv[0] = (t > 0)        ? xb[t - 1] : 0.f;
    xv[9] = (t + 8 < T_)   ? xb[t + 8] : 0.f;
    float o[8];
    #pragma unroll
    for (int e = 0; e < 8; e++) {
        float v = fmaf(w0, xv[e], fmaf(w1, xv[e + 1], w2 * xv[e + 2])) + bb;
        o[e] = gelu_exact(v);
    }
    float* op = g_q + (size_t)(b * D_ + d) * T_ + t;
    *(float4*)op       = make_float4(o[0], o[1], o[2], o[3]);
    *(float4*)(op + 4) = make_float4(o[4], o[5], o[6], o[7]);
}

// ---------------------------------------------------------------------------
// Kernel B: fused banded energy + softmax + context. 512 threads/block.
// sq[d][w] = q[d][t0-64+w], w in [0,96). Band for row t: w in [t+1, t+64].
// smem: sq[512][100] + E0[32][96] + E1[32][96] = 229,376 B
// Energy: band-trimmed — each t-quad computes 5 of 6 j-blocks (j0 = ty>>2).
// ---------------------------------------------------------------------------
extern __shared__ float smem[];

__global__ void __launch_bounds__(512, 1)
attn_kernel(const float* __restrict__ gate, float* __restrict__ out) {
    float* sq = smem;                     // [512][100]
    float* E0 = smem + D_ * WP;           // [32][96]
    float* E1 = E0 + TT * MP;             // [32][96]

    const int tid = threadIdx.x;
    const int b   = blockIdx.y;
    const int t0  = blockIdx.x * TT;
    const float tgate = tanhf(gate[0]);

    const int qz = tid >> 6;      // D group (0..7), 64 threads each
    const int r  = tid & 63;

    // ---- window load: cp.async per D-group (64 rows), named-barrier sync ----
    {
        const float* qbase = g_q + (size_t)b * D_ * T_
                             + (size_t)(64 * qz) * T_ + t0 - 64;
        float* sbase = sq + 64 * qz * WP;
        #pragma unroll
        for (int k = 0; k < 24; ++k) {
            int f  = r + k * 64;             // quad index over 64 rows x 24 quads
            int dl = f / 24, q = f - dl * 24;
            int wq = 4 * q;
            const float* src = qbase + (size_t)dl * T_ + wq;
            unsigned daddr =
                (unsigned)__cvta_generic_to_shared(sbase + dl * WP + wq);
            if (t0 - 64 + wq >= 0)
                asm volatile("cp.async.ca.shared.global [%0], [%1], 16;"
                             :: "r"(daddr), "l"(src));
            else  // zero-fill left pad
                asm volatile("cp.async.ca.shared.global [%0], [%1], 16, 0;"
                             :: "r"(daddr), "l"(src));
        }
        asm volatile("cp.async.commit_group;");
        asm volatile("cp.async.wait_group 0;" ::: "memory");
        asm volatile("bar.sync %0, %1;" :: "r"(qz + 1), "r"(64) : "memory");
    }

    // ---- energy: band-trimmed; per thread 4t x 10w-pairs (5 j-blocks) ----
    {
        const int tx = r & 7;         // w pair: w = 2*tx + 16*(j+j0) (+0/1)
        const int ty = r >> 3;        // t quad: t = 4*ty + i, i=0..3
        const int j0 = ty >> 2;       // 0 for t<16, 1 for t>=16 (band shift)
        u64 acc2[4][5];
        #pragma unroll
        for (int i = 0; i < 4; i++)
            #pragma unroll
            for (int j = 0; j < 5; j++) acc2[i][j] = 0ull;

        const float* sqd = sq + qz * 64 * WP;
        const int wbase = 2 * tx + 16 * j0;
        #pragma unroll 2
        for (int d = 0; d < 64; ++d) {
            const float* row = sqd + d * WP;
            float4 af = *(const float4*)(row + 64 + 4 * ty);  // broadcast LDS.128
            u64 a2[4];
            PACKDUP(a2[0], af.x);
            PACKDUP(a2[1], af.y);
            PACKDUP(a2[2], af.z);
            PACKDUP(a2[3], af.w);
            u64 bv2[5];
            #pragma unroll
            for (int j = 0; j < 5; j++)
                bv2[j] = *(const u64*)(row + wbase + 16 * j);
            #pragma unroll
            for (int i = 0; i < 4; i++)
                #pragma unroll
                for (int j = 0; j < 5; j++)
                    FMA2(acc2[i][j], a2[i], bv2[j], acc2[i][j]);
        }
        // accumulate 8 group-partials into 2 buffers in 4 phases
        float* Eo = (qz & 1) ? E1 : E0;
        const int phase = qz >> 1;
        if (phase == 0) {
            #pragma unroll
            for (int i = 0; i < 4; i++)
                #pragma unroll
                for (int j = 0; j < 5; j++)
                    *(u64*)(Eo + (4 * ty + i) * MP + wbase + 16 * j) = acc2[i][j];
        }
        __syncthreads();
        #pragma unroll
        for (int p = 1; p < 4; ++p) {
            if (phase == p) {
                #pragma unroll
                for (int i = 0; i < 4; i++)
                    #pragma unroll
                    for (int j = 0; j < 5; j++) {
                        u64* ptr = (u64*)(Eo + (4 * ty + i) * MP + wbase + 16 * j);
                        u64 v = *ptr;
                        ADD2(v, v, acc2[i][j]);
                        *ptr = v;
                    }
            }
            __syncthreads();
        }
    }

    // ---- softmax over k; band w in [t+1, t+64]; attn into E0, zeros elsewhere ----
    {
        const int warp = tid >> 5, lane = tid & 31;  // 16 warps, 2 rows each
        const float S = 0.04419417382415922f;        // 1/sqrt(512)
        #pragma unroll
        for (int t = warp; t < TT; t += 16) {
            float e1 = E0[t * MP + t + 1 + lane]  + E1[t * MP + t + 1 + lane];
            float e2 = E0[t * MP + t + 33 + lane] + E1[t * MP + t + 33 + lane];
            float mx = fmaxf(e1, e2);
            #pragma unroll
            for (int o = 16; o; o >>= 1) mx = fmaxf(mx, __shfl_xor_sync(0xffffffffu, mx, o));
            float p1 = __expf((e1 - mx) * S);
            float p2 = __expf((e2 - mx) * S);
            float sm = p1 + p2;
            #pragma unroll
            for (int o = 16; o; o >>= 1) sm += __shfl_xor_sync(0xffffffffu, sm, o);
            float inv = 1.f / sm;
            E0[t * MP + lane]      = 0.f;
            E0[t * MP + lane + 32] = 0.f;
            E0[t * MP + lane + 64] = 0.f;
            E0[t * MP + t + 1 + lane]  = p1 * inv;
            E0[t * MP + t + 33 + lane] = p2 * inv;
        }
    }
    __syncthreads();

    // ---- context: C[t][d] = sum_w attn[t][w] * sq[d][w]; 8t x 4d per thread ----
    {
        const int tx = tid & 127;  // d lane: d = tx + 128*j, j=0..3
        const int ty = tid >> 7;   // t group: t = 8*ty + i, i=0..7
        const int w0 = 8 * ty;     // band union [8ty+1, 8ty+71] within [w0, w0+72)
        u64 acc2[8][4];
        #pragma unroll
        for (int i = 0; i < 8; i++)
            #pragma unroll
            for (int j = 0; j < 4; j++) acc2[i][j] = 0ull;

        const float* bbase = sq + tx * WP;
        const float* abase = E0 + 8 * ty * MP;
        #pragma unroll 2
        for (int s = 0; s < 18; ++s) {
            const int w = w0 + 4 * s;
            // i in two chunks of 4 to bound register pressure
            #pragma unroll
            for (int ih = 0; ih < 2; ++ih) {
                ulonglong2 av[4];
                #pragma unroll
                for (int i = 0; i < 4; i++)
                    av[i] = *(const ulonglong2*)(abase + (4 * ih + i) * MP + w);
                #pragma unroll
                for (int j = 0; j < 4; j++) {
                    ulonglong2 bv = *(const ulonglong2*)(bbase + j * 128 * WP + w);
                    #pragma unroll
                    for (int i = 0; i < 4; i++) {
                        FMA2(acc2[4 * ih + i][j], av[i].x, bv.x, acc2[4 * ih + i][j]);
                        FMA2(acc2[4 * ih + i][j], av[i].y, bv.y, acc2[4 * ih + i][j]);
                    }
                }
            }
        }
        // horizontal add + direct STG.128: 8 consecutive t per thread
        #pragma unroll
        for (int j = 0; j < 4; j++) {
            float c[8];
            #pragma unroll
            for (int i = 0; i < 8; i++) {
                float2 p = *(float2*)&acc2[i][j];
                c[i] = (p.x + p.y) * tgate;
            }
            float* op = out + (size_t)(b * D_ + tx + 128 * j) * T_ + t0 + 8 * ty;
            *(float4*)op       = make_float4(c[0], c[1], c[2], c[3]);
            *(float4*)(op + 4) = make_float4(c[4], c[5], c[6], c[7]);
        }
    }
}

// ---------------------------------------------------------------------------
extern "C" void kernel_launch(void* const* d_in, const int* in_sizes, int n_in,
                              void* d_out, int out_size) {
    const float* x      = (const float*)d_in[0];  // (2,1,2048)
    const float* conv_w = (const float*)d_in[1];  // (512,1,3)
    const float* conv_b = (const float*)d_in[2];  // (512,)
    const float* gate   = (const float*)d_in[3];  // scalar
    float* out = (float*)d_out;                   // (2,512,2048)

    (void)in_sizes; (void)n_in; (void)out_size;

    dim3 gA(T_ / 1024, D_, B_);
    conv_gelu_kernel<<<gA, 128>>>(x, conv_w, conv_b);

    const int smem_bytes = (D_ * WP + 2 * TT * MP) * (int)sizeof(float); // 229,376
    cudaFuncSetAttribute(attn_kernel, cudaFuncAttributeMaxDynamicSharedMemorySize, smem_bytes);
    dim3 gB(T_ / TT, B_);
    attn_kernel<<<gB, 512, smem_bytes>>>(gate, out);
}